// round 15
// baseline (speedup 1.0000x reference)
#include <cuda_runtime.h>
#include <cuda_fp16.h>

#define NN    4096
#define BB    256
#define VOC   200
#define TT    128
#define LVG   740
#define NPAIR (VOC * VOC)

// ---------------- scratch (device globals; no allocation) ----------------
static __device__ float4 g_h4[(size_t)NN * 8 * BB];      // [node][q][b]
static __device__ float4 g_p4[128 * 8 * BB];             // root partials
static __device__ float g_Pa[VOC * 32];                  // fp32 (root use)
static __device__ float g_Pb[VOC * 32];
static __device__ __align__(16) __half g_PcH[(size_t)NPAIR * 32];  // combined pair table
static __device__ __align__(16) __half g_LcH[(size_t)NPAIR * 32];  // combined leaf table
static __device__ float g_F[BB * 32];
static __device__ float g_Lt[(size_t)BB * TT * 32];
static __device__ float g_v[32];
static __device__ float g_s;
static __device__ int   g_cnt[NN];
static __device__ int   g_cur[NN];
static __device__ int   g_off[NN + 1];
static __device__ int   g_child[NN];
static __device__ int   g_lvcnt[8];
static __device__ int   g_lvnodes[6 * NN];
static __device__ int   g_tC[NN * BB];                   // fused ta*200+tb, [p][b]
static __device__ int   g_tP[NN * BB];

// ---------------- f32x2 helpers ----------------
__device__ __forceinline__ unsigned long long pack2(float lo, float hi) {
    unsigned long long r;
    asm("mov.b64 %0, {%1, %2};" : "=l"(r) : "r"(__float_as_uint(lo)), "r"(__float_as_uint(hi)));
    return r;
}
__device__ __forceinline__ void unpack2(unsigned long long v, float& lo, float& hi) {
    unsigned int a, b;
    asm("mov.b64 {%0, %1}, %2;" : "=r"(a), "=r"(b) : "l"(v));
    lo = __uint_as_float(a);
    hi = __uint_as_float(b);
}
__device__ __forceinline__ void fma2(unsigned long long& d, unsigned long long a, unsigned long long b) {
    asm("fma.rn.f32x2 %0, %1, %2, %0;" : "+l"(d) : "l"(a), "l"(b));
}
__device__ __forceinline__ unsigned long long add2(unsigned long long a, unsigned long long b) {
    unsigned long long r;
    asm("add.rn.f32x2 %0, %1, %2;" : "=l"(r) : "l"(a), "l"(b));
    return r;
}

// gather ONE fp16 combined row -> 16 packed f32x2
__device__ __forceinline__ void gather_one_h(const __half* Pc, int tc, unsigned long long* o) {
    const uint4* A = (const uint4*)(Pc + (size_t)tc * 32);
    #pragma unroll
    for (int q = 0; q < 4; q++) {
        uint4 x = A[q];
        unsigned xs[4] = {x.x, x.y, x.z, x.w};
        #pragma unroll
        for (int r = 0; r < 4; r++) {
            float2 f = __half22float2(*(const __half2*)&xs[r]);
            o[q * 4 + r] = pack2(f.x, f.y);
        }
    }
}

// ============ prep roles:
//   [0,1024)    fused token transpose -> g_tC
//   [1024,2048) ptr_time transpose   -> g_tP
//   [2048,3072) Lt
//   [3072,3104) F
//   [3104,4704) combined pair tables (PcH/LcH, computed from first principles)
//   4704        serial: CSR/scan/fuse/root-tables
__global__ void __launch_bounds__(256) k_prep(
    const int* __restrict__ parent, const int* __restrict__ height,
    const int* __restrict__ tok_a, const int* __restrict__ tok_b,
    const int* __restrict__ ptr_time,
    const float* __restrict__ lstm, const float* __restrict__ fn,
    const float* __restrict__ pw, const float* __restrict__ pbias,
    const float* __restrict__ lw1, const float* __restrict__ lb1,
    const float* __restrict__ lw2, const float* __restrict__ lb2,
    const float* __restrict__ fw1, const float* __restrict__ fb1,
    const float* __restrict__ fw2, const float* __restrict__ fb2,
    const float* __restrict__ tw, const float* __restrict__ tb,
    const float* __restrict__ emb, const float* __restrict__ node_w,
    const float* __restrict__ node_b)
{
    int bid = blockIdx.x, t = threadIdx.x;
    if (bid < 1024) {
        // fused transpose: tC[p][b] = tok_a[b][p]*200 + tok_b[b][p]
        __shared__ int tile[32][33];
        int pt = bid >> 3, bt = bid & 7;
        int x = t & 31, y0 = t >> 5;
        #pragma unroll
        for (int y = y0; y < 32; y += 8) {
            size_t idx = (size_t)(bt * 32 + y) * NN + pt * 32 + x;
            tile[y][x] = tok_a[idx] * VOC + tok_b[idx];
        }
        __syncthreads();
        #pragma unroll
        for (int y = y0; y < 32; y += 8)
            g_tC[(size_t)(pt * 32 + y) * BB + bt * 32 + x] = tile[x][y];
    } else if (bid < 2048) {
        __shared__ int tile[32][33];
        int tl = bid - 1024;
        int pt = tl >> 3, bt = tl & 7;
        int x = t & 31, y0 = t >> 5;
        #pragma unroll
        for (int y = y0; y < 32; y += 8)
            tile[y][x] = ptr_time[(size_t)(bt * 32 + y) * NN + pt * 32 + x];
        __syncthreads();
        #pragma unroll
        for (int y = y0; y < 32; y += 8)
            g_tP[(size_t)(pt * 32 + y) * BB + bt * 32 + x] = tile[x][y];
    } else if (bid < 3072) {
        // Lt: warp computes 4 rows x 32 cols. 8192 warps total.
        int wg = (bid - 2048) * 8 + (t >> 5);   // 0..8191
        int j = t & 31;
        int r0 = wg * 4;
        const float4* l0 = (const float4*)(lstm + (size_t)r0 * 64);
        float a0 = 0.f, a1 = 0.f, a2 = 0.f, a3 = 0.f;
        #pragma unroll
        for (int k4 = 0; k4 < 16; k4++) {
            float4 v0 = __ldg(l0 + k4);
            float4 v1 = __ldg(l0 + 16 + k4);
            float4 v2 = __ldg(l0 + 32 + k4);
            float4 v3 = __ldg(l0 + 48 + k4);
            float w0 = __ldg(pw + (64 + 4 * k4 + 0) * 32 + j);
            float w1 = __ldg(pw + (64 + 4 * k4 + 1) * 32 + j);
            float w2 = __ldg(pw + (64 + 4 * k4 + 2) * 32 + j);
            float w3 = __ldg(pw + (64 + 4 * k4 + 3) * 32 + j);
            a0 += v0.x * w0 + v0.y * w1 + v0.z * w2 + v0.w * w3;
            a1 += v1.x * w0 + v1.y * w1 + v1.z * w2 + v1.w * w3;
            a2 += v2.x * w0 + v2.y * w1 + v2.z * w2 + v2.w * w3;
            a3 += v3.x * w0 + v3.y * w1 + v3.z * w2 + v3.w * w3;
        }
        g_Lt[(size_t)(r0 + 0) * 32 + j] = a0;
        g_Lt[(size_t)(r0 + 1) * 32 + j] = a1;
        g_Lt[(size_t)(r0 + 2) * 32 + j] = a2;
        g_Lt[(size_t)(r0 + 3) * 32 + j] = a3;
    } else if (bid < 3104) {
        // F: 8192 outputs, 1 per thread
        int gid = (bid - 3072) * 256 + t;
        int b = gid >> 5, j = gid & 31;
        float s = pbias[j];
        #pragma unroll
        for (int k = 0; k < 64; k++)
            s += __ldg(fn + b * 64 + k) * __ldg(pw + k * 32 + j);
        g_F[b * 32 + j] = s;
    } else if (bid < 4704) {
        // combined pair tables: block = (ta, 25-tb chunk). 200 ta x 8 chunks = 1600 blocks.
        __shared__ float Wlsh[1024];
        __shared__ float blsh[32];
        int bid2 = bid - 3104;
        int ta = bid2 >> 3, tb0 = (bid2 & 7) * 25;
        int j = t & 31, tl0 = t >> 5;
        // fused leaf weight matrix (recomputed per block; trivial)
        #pragma unroll
        for (int rep = 0; rep < 4; rep++) {
            int idx = t + rep * 256;
            int i = idx >> 5, jj = idx & 31;
            float s = 0.f;
            for (int k = 0; k < 32; k++) s += lw1[i * 32 + k] * lw2[k * 32 + jj];
            Wlsh[idx] = s;
        }
        if (t < 32) {
            float bsum = lb2[t];
            for (int k = 0; k < 32; k++) bsum += lb1[k] * lw2[k * 32 + t];
            blsh[t] = bsum;
        }
        __syncthreads();
        // per-ta parts (column j)
        float pa = node_b[j], la = blsh[j];
        #pragma unroll
        for (int e = 0; e < 16; e++) {
            float ev = __ldg(emb + ta * 16 + e);
            pa += ev * node_w[e * 32 + j];
            la += ev * Wlsh[e * 32 + j];
        }
        // per-tb parts: 8 threads-groups x 4 iters = 32 slots covering 25 tb
        #pragma unroll
        for (int it = 0; it < 4; it++) {
            int tbl = tl0 + it * 8;
            if (tbl < 25) {
                int tbv = tb0 + tbl;
                float pb = 0.f, lb = 0.f;
                #pragma unroll
                for (int e = 0; e < 16; e++) {
                    float ev = __ldg(emb + tbv * 16 + e);
                    pb += ev * node_w[(16 + e) * 32 + j];
                    lb += ev * Wlsh[(16 + e) * 32 + j];
                }
                size_t o = ((size_t)ta * VOC + tbv) * 32 + j;
                g_PcH[o] = __float2half(pa + pb);
                g_LcH[o] = __float2half(la + lb);
            }
        }
    } else {
        __shared__ int sc[256];
        __shared__ float u[32];
        __shared__ float Wlsh[1024];
        __shared__ float blsh[32];
        for (int i = t; i < NN; i += 256) { g_cnt[i] = 0; g_cur[i] = 0; }
        if (t < 8) g_lvcnt[t] = 0;
        __syncthreads();
        for (int c = t; c < NN; c += 256)
            if (c >= 1) atomicAdd(&g_cnt[parent[c]], 1);
        __syncthreads();
        int base = t * 16;
        int loc[16];
        int run = 0;
        #pragma unroll
        for (int r = 0; r < 16; r++) { loc[r] = run; run += g_cnt[base + r]; }
        sc[t] = run;
        __syncthreads();
        for (int off = 1; off < 256; off <<= 1) {
            int v = (t >= off) ? sc[t - off] : 0;
            __syncthreads();
            sc[t] += v;
            __syncthreads();
        }
        int excl = sc[t] - run;
        #pragma unroll
        for (int r = 0; r < 16; r++) g_off[base + r] = excl + loc[r];
        if (t == 255) g_off[NN] = sc[255];
        __syncthreads();
        for (int c = t; c < NN; c += 256) {
            if (c >= 1) {
                int p = parent[c];
                int pos = atomicAdd(&g_cur[p], 1);
                g_child[g_off[p] + pos] = c;
            }
            int h = height[c];
            if (h < 6) {
                int i = atomicAdd(&g_lvcnt[h], 1);
                g_lvnodes[h * NN + i] = c;
            }
        }
        // fused leaf weights (for readout vector only)
        for (int idx = t; idx < 1024; idx += 256) {
            int i = idx >> 5, j = idx & 31;
            float s = 0.f;
            for (int k = 0; k < 32; k++) s += lw1[i * 32 + k] * lw2[k * 32 + j];
            Wlsh[idx] = s;
        }
        if (t < 32) {
            float bsum = lb2[t];
            for (int k = 0; k < 32; k++) bsum += lb1[k] * lw2[k * 32 + t];
            blsh[t] = bsum;
            float uu = 0.f;
            for (int q = 0; q < 32; q++) uu += fw2[t * 32 + q] * tw[q];
            u[t] = uu;
        }
        __syncthreads();
        if (t < 32) {
            float vv = 0.f;
            for (int k = 0; k < 32; k++) vv += fw1[t * 32 + k] * u[k];
            g_v[t] = vv;
        }
        if (t == 0) {
            float ss = tb[0];
            for (int k = 0; k < 32; k++) ss += fb1[k] * u[k];
            for (int q = 0; q < 32; q++) ss += fb2[q] * tw[q];
            g_s = ss;
        }
        // fp32 root tables
        for (int idx = t; idx < VOC * 32; idx += 256) {
            int v = idx >> 5, jj = idx & 31;
            float pa = node_b[jj], pb = 0.f;
            for (int e = 0; e < 16; e++) {
                float ev = emb[v * 16 + e];
                pa += ev * node_w[e * 32 + jj];
                pb += ev * node_w[(16 + e) * 32 + jj];
            }
            g_Pa[idx] = pa;
            g_Pb[idx] = pb;
        }
    }
}

// ============ leaf init: single combined fp16 gather ============
__global__ void __launch_bounds__(256, 4) k_init(const int* __restrict__ kind) {
    int cnt = g_lvcnt[0];
    int b = threadIdx.x;
    for (int ni = blockIdx.x; ni < cnt; ni += gridDim.x) {
        int node = g_lvnodes[ni];
        int kd = kind[node];
        float4 r[8];
        if (kd == 0) {
            int tc = g_tC[node * BB + b];
            unsigned long long o[16];
            gather_one_h(g_LcH, tc, o);
            #pragma unroll
            for (int q = 0; q < 8; q++) {
                float x0, x1, x2, x3;
                unpack2(o[2 * q], x0, x1);
                unpack2(o[2 * q + 1], x2, x3);
                r[q] = make_float4(x0, x1, x2, x3);
            }
        } else {
            int tm = g_tP[node * BB + b];
            const float4* A  = (const float4*)(g_F + b * 32);
            const float4* Bv = (const float4*)(g_Lt + ((size_t)b * TT + tm) * 32);
            #pragma unroll
            for (int q = 0; q < 8; q++) {
                float4 x = A[q], y = Bv[q];
                r[q] = make_float4(x.x + y.x, x.y + y.y, x.z + y.z, x.w + y.w);
            }
        }
        float4* dst = g_h4 + (size_t)node * 2048 + b;
        #pragma unroll
        for (int q = 0; q < 8; q++) dst[q * 256] = r[q];
    }
}

// ============ level: 128 thr/node, (128,5), stride-35 csum, no in-loop syncs ============
__global__ void __launch_bounds__(128, 5) k_level(const float* __restrict__ node_w, int lvl) {
    __shared__ __align__(16) unsigned long long Wsh[512];   // 4KB
    __shared__ float csum[256 * 35];                        // 35.8KB, self-access only
    int cnt = g_lvcnt[lvl];
    int t = threadIdx.x;
    ((ulonglong2*)Wsh)[t]       = ((const ulonglong2*)(node_w + 1024))[t];
    ((ulonglong2*)Wsh)[t + 128] = ((const ulonglong2*)(node_w + 1024))[t + 128];
    __syncthreads();                                        // Wsh visible to all warps
    if ((int)blockIdx.x >= cnt) return;
    const int* list = g_lvnodes + lvl * NN;
    for (int ni = blockIdx.x; ni < cnt; ni += gridDim.x) {
        int node = list[ni];
        int c0 = g_off[node], c1 = g_off[node + 1];
        int tc0 = g_tC[node * BB + t];
        int tc1 = g_tC[node * BB + t + 128];
        // phase 1: children sums for b=t and b=t+128, staged to private smem rows
        #pragma unroll
        for (int hf = 0; hf < 2; hf++) {
            int b = t + hf * 128;
            float4 a[8];
            #pragma unroll
            for (int q = 0; q < 8; q++) a[q] = make_float4(0.f, 0.f, 0.f, 0.f);
            for (int ci = c0; ci < c1; ci++) {
                int c = g_child[ci];
                const float4* src = g_h4 + (size_t)c * 2048 + b;
                #pragma unroll
                for (int q = 0; q < 8; q++) {
                    float4 v = src[q * 256];
                    a[q].x += v.x; a[q].y += v.y; a[q].z += v.z; a[q].w += v.w;
                }
            }
            const float* af = (const float*)a;
            #pragma unroll
            for (int k = 0; k < 32; k++) csum[b * 35 + k] = af[k];
        }
        // phase 2: single combined gathers + dual matvec (csum rows are this thread's own)
        int b0 = t, b1 = t + 128;
        unsigned long long oA[16], oB[16];
        gather_one_h(g_PcH, tc0, oA);
        gather_one_h(g_PcH, tc1, oB);
        #pragma unroll
        for (int kk = 0; kk < 32; kk++) {
            float s0 = csum[b0 * 35 + kk];
            float s1 = csum[b1 * 35 + kk];
            unsigned long long a0 = pack2(s0, s0);
            unsigned long long a1 = pack2(s1, s1);
            const ulonglong2* wrow = (const ulonglong2*)(Wsh + kk * 16);
            #pragma unroll
            for (int j2 = 0; j2 < 8; j2++) {
                ulonglong2 w = wrow[j2];
                fma2(oA[2 * j2], a0, w.x);
                fma2(oA[2 * j2 + 1], a0, w.y);
                fma2(oB[2 * j2], a1, w.x);
                fma2(oB[2 * j2 + 1], a1, w.y);
            }
        }
        float4* d0 = g_h4 + (size_t)node * 2048 + b0;
        float4* d1 = g_h4 + (size_t)node * 2048 + b1;
        #pragma unroll
        for (int q = 0; q < 8; q++) {
            float l0, h0, l1, h1;
            unpack2(oA[2 * q], l0, h0);
            unpack2(oA[2 * q + 1], l1, h1);
            d0[q * 256] = make_float4(fmaxf(l0, 0.f), fmaxf(h0, 0.f),
                                      fmaxf(l1, 0.f), fmaxf(h1, 0.f));
            unpack2(oB[2 * q], l0, h0);
            unpack2(oB[2 * q + 1], l1, h1);
            d1[q * 256] = make_float4(fmaxf(l0, 0.f), fmaxf(h0, 0.f),
                                      fmaxf(l1, 0.f), fmaxf(h1, 0.f));
        }
    }
}

// ============ root partial sums (128 blocks) ============
__global__ void __launch_bounds__(256) k_f1() {
    int b = threadIdx.x, s = blockIdx.x;
    float4 acc[8];
    #pragma unroll
    for (int q = 0; q < 8; q++) acc[q] = make_float4(0.f, 0.f, 0.f, 0.f);
    int c0 = g_off[0], c1 = g_off[1];
    for (int ci = c0 + s; ci < c1; ci += 128) {
        int c = g_child[ci];
        const float4* src = g_h4 + (size_t)c * 2048 + b;
        #pragma unroll
        for (int q = 0; q < 8; q++) {
            float4 v = src[q * 256];
            acc[q].x += v.x; acc[q].y += v.y; acc[q].z += v.z; acc[q].w += v.w;
        }
    }
    float4* dst = g_p4 + (size_t)s * 2048 + b;
    #pragma unroll
    for (int q = 0; q < 8; q++) dst[q * 256] = acc[q];
}

// ============ root stage 2: 128 -> 16 partials ============
__global__ void __launch_bounds__(256) k_f2() {
    int b = threadIdx.x, s = blockIdx.x;      // s in 0..15
    float4 acc[8];
    #pragma unroll
    for (int q = 0; q < 8; q++) acc[q] = make_float4(0.f, 0.f, 0.f, 0.f);
    #pragma unroll
    for (int i = 0; i < 8; i++) {
        const float4* src = g_p4 + (size_t)(s + 16 * i) * 2048 + b;
        #pragma unroll
        for (int q = 0; q < 8; q++) {
            float4 v = src[q * 256];
            acc[q].x += v.x; acc[q].y += v.y; acc[q].z += v.z; acc[q].w += v.w;
        }
    }
    float4* dst = g_p4 + (size_t)s * 2048 + b;
    #pragma unroll
    for (int q = 0; q < 8; q++) dst[q * 256] = acc[q];
}

// ============ root finish (1 block, 16 partials, fp32 tables) ============
__global__ void __launch_bounds__(256) k_f23(const float* __restrict__ node_w,
                                             float* __restrict__ out) {
    int b = threadIdx.x;
    float4 acc[8];
    #pragma unroll
    for (int q = 0; q < 8; q++) acc[q] = make_float4(0.f, 0.f, 0.f, 0.f);
    #pragma unroll
    for (int s = 0; s < 16; s++) {
        const float4* src = g_p4 + (size_t)s * 2048 + b;
        #pragma unroll
        for (int q = 0; q < 8; q++) {
            float4 v = src[q * 256];
            acc[q].x += v.x; acc[q].y += v.y; acc[q].z += v.z; acc[q].w += v.w;
        }
    }
    int tc = g_tC[b];                       // node 0, batch b
    int ta = tc / VOC, tb = tc - (tc / VOC) * VOC;
    unsigned long long o2[16];
    #pragma unroll
    for (int q = 0; q < 8; q++) {
        ulonglong2 x = ((const ulonglong2*)(g_Pa + ta * 32))[q];
        ulonglong2 y = ((const ulonglong2*)(g_Pb + tb * 32))[q];
        o2[2 * q]     = add2(x.x, y.x);
        o2[2 * q + 1] = add2(x.y, y.y);
    }
    const float* af = (const float*)acc;
    #pragma unroll
    for (int k = 0; k < 32; k++) {
        unsigned long long a2 = pack2(af[k], af[k]);
        const ulonglong2* wrow = (const ulonglong2*)(node_w + 1024 + k * 32);
        #pragma unroll
        for (int j2 = 0; j2 < 8; j2++) {
            ulonglong2 w = wrow[j2];
            fma2(o2[2 * j2], a2, w.x);
            fma2(o2[2 * j2 + 1], a2, w.y);
        }
    }
    float val = 0.f;
    #pragma unroll
    for (int q = 0; q < 8; q++) {
        float l0, h0, l1, h1;
        unpack2(o2[2 * q], l0, h0);
        unpack2(o2[2 * q + 1], l1, h1);
        val += fmaxf(l0, 0.f) * g_v[4 * q]     + fmaxf(h0, 0.f) * g_v[4 * q + 1]
             + fmaxf(l1, 0.f) * g_v[4 * q + 2] + fmaxf(h1, 0.f) * g_v[4 * q + 3];
    }
    out[b] = val + g_s;
}

// ---------------- launch ----------------
extern "C" void kernel_launch(void* const* d_in, const int* in_sizes, int n_in,
                              void* d_out, int out_size) {
    const int*   kind        = (const int*)d_in[0];
    const int*   height      = (const int*)d_in[1];
    const int*   parent      = (const int*)d_in[2];
    const int*   tok_a       = (const int*)d_in[3];
    const int*   tok_b       = (const int*)d_in[4];
    const int*   ptr_time    = (const int*)d_in[5];
    const float* first_notes = (const float*)d_in[6];
    const float* lstm_out    = (const float*)d_in[7];
    const float* embedding   = (const float*)d_in[8];
    const float* leaf_w1     = (const float*)d_in[9];
    const float* leaf_b1     = (const float*)d_in[10];
    const float* leaf_w2     = (const float*)d_in[11];
    const float* leaf_b2     = (const float*)d_in[12];
    const float* node_w      = (const float*)d_in[13];
    const float* node_b      = (const float*)d_in[14];
    const float* ptr_w       = (const float*)d_in[15];
    const float* ptr_b       = (const float*)d_in[16];
    const float* ff_w1       = (const float*)d_in[17];
    const float* ff_b1       = (const float*)d_in[18];
    const float* ff_w2       = (const float*)d_in[19];
    const float* ff_b2       = (const float*)d_in[20];
    const float* tail_w      = (const float*)d_in[21];
    const float* tail_b      = (const float*)d_in[22];
    float* out = (float*)d_out;

    k_prep<<<4705, 256>>>(parent, height, tok_a, tok_b, ptr_time,
                          lstm_out, first_notes, ptr_w, ptr_b,
                          leaf_w1, leaf_b1, leaf_w2, leaf_b2,
                          ff_w1, ff_b1, ff_w2, ff_b2, tail_w, tail_b,
                          embedding, node_w, node_b);
    k_init<<<LVG, 256>>>(kind);
    for (int lvl = 1; lvl <= 5; lvl++)
        k_level<<<LVG, 128>>>(node_w, lvl);
    k_f1<<<128, 256>>>();
    k_f2<<<16, 256>>>();
    k_f23<<<1, 256>>>(node_w, out);
}

// round 16
// speedup vs baseline: 1.4113x; 1.4113x over previous
#include <cuda_runtime.h>
#include <cuda_fp16.h>

#define NN    4096
#define BB    256
#define VOC   200
#define TT    128
#define LVG   740
#define NPAIR (VOC * VOC)

// ---------------- scratch (device globals; no allocation) ----------------
static __device__ float4 g_h4[(size_t)NN * 8 * BB];      // [node][q][b]
static __device__ float4 g_p4[128 * 8 * BB];             // root partials
static __device__ float g_Pa[VOC * 32];                  // fp32 (root use)
static __device__ float g_Pb[VOC * 32];
static __device__ __align__(16) __half g_PcH[(size_t)NPAIR * 32];  // combined pair table
static __device__ __align__(16) __half g_LcH[(size_t)NPAIR * 32];  // combined leaf table
static __device__ float g_F[BB * 32];
static __device__ float g_Lt[(size_t)BB * TT * 32];
static __device__ float g_v[32];
static __device__ float g_s;
static __device__ int   g_cnt[NN];
static __device__ int   g_cur[NN];
static __device__ int   g_off[NN + 1];
static __device__ int   g_child[NN];
static __device__ int   g_lvcnt[8];
static __device__ int   g_lvnodes[6 * NN];
static __device__ int   g_tC[NN * BB];                   // fused ta*200+tb, [p][b]
static __device__ int   g_tP[NN * BB];

// ---------------- f32x2 helpers ----------------
__device__ __forceinline__ unsigned long long pack2(float lo, float hi) {
    unsigned long long r;
    asm("mov.b64 %0, {%1, %2};" : "=l"(r) : "r"(__float_as_uint(lo)), "r"(__float_as_uint(hi)));
    return r;
}
__device__ __forceinline__ void unpack2(unsigned long long v, float& lo, float& hi) {
    unsigned int a, b;
    asm("mov.b64 {%0, %1}, %2;" : "=r"(a), "=r"(b) : "l"(v));
    lo = __uint_as_float(a);
    hi = __uint_as_float(b);
}
__device__ __forceinline__ void fma2(unsigned long long& d, unsigned long long a, unsigned long long b) {
    asm("fma.rn.f32x2 %0, %1, %2, %0;" : "+l"(d) : "l"(a), "l"(b));
}
__device__ __forceinline__ unsigned long long add2(unsigned long long a, unsigned long long b) {
    unsigned long long r;
    asm("add.rn.f32x2 %0, %1, %2;" : "=l"(r) : "l"(a), "l"(b));
    return r;
}

// gather ONE fp16 combined row -> 16 packed f32x2
__device__ __forceinline__ void gather_one_h(const __half* Pc, int tc, unsigned long long* o) {
    const uint4* A = (const uint4*)(Pc + (size_t)tc * 32);
    #pragma unroll
    for (int q = 0; q < 4; q++) {
        uint4 x = A[q];
        unsigned xs[4] = {x.x, x.y, x.z, x.w};
        #pragma unroll
        for (int r = 0; r < 4; r++) {
            float2 f = __half22float2(*(const __half2*)&xs[r]);
            o[q * 4 + r] = pack2(f.x, f.y);
        }
    }
}

// ============ prep roles:
//   [0,1024)    fused token transpose -> g_tC
//   [1024,2048) ptr_time transpose   -> g_tP
//   [2048,3072) Lt
//   [3072,3104) F
//   [3104,4704) combined pair tables (PcH/LcH)
//   4704        serial: CSR/scan/fuse/root-tables
__global__ void __launch_bounds__(256) k_prep(
    const int* __restrict__ parent, const int* __restrict__ height,
    const int* __restrict__ tok_a, const int* __restrict__ tok_b,
    const int* __restrict__ ptr_time,
    const float* __restrict__ lstm, const float* __restrict__ fn,
    const float* __restrict__ pw, const float* __restrict__ pbias,
    const float* __restrict__ lw1, const float* __restrict__ lb1,
    const float* __restrict__ lw2, const float* __restrict__ lb2,
    const float* __restrict__ fw1, const float* __restrict__ fb1,
    const float* __restrict__ fw2, const float* __restrict__ fb2,
    const float* __restrict__ tw, const float* __restrict__ tb,
    const float* __restrict__ emb, const float* __restrict__ node_w,
    const float* __restrict__ node_b)
{
    int bid = blockIdx.x, t = threadIdx.x;
    if (bid < 1024) {
        // fused transpose: tC[p][b] = tok_a[b][p]*200 + tok_b[b][p]
        __shared__ int tile[32][33];
        int pt = bid >> 3, bt = bid & 7;
        int x = t & 31, y0 = t >> 5;
        #pragma unroll
        for (int y = y0; y < 32; y += 8) {
            size_t idx = (size_t)(bt * 32 + y) * NN + pt * 32 + x;
            tile[y][x] = tok_a[idx] * VOC + tok_b[idx];
        }
        __syncthreads();
        #pragma unroll
        for (int y = y0; y < 32; y += 8)
            g_tC[(size_t)(pt * 32 + y) * BB + bt * 32 + x] = tile[x][y];
    } else if (bid < 2048) {
        __shared__ int tile[32][33];
        int tl = bid - 1024;
        int pt = tl >> 3, bt = tl & 7;
        int x = t & 31, y0 = t >> 5;
        #pragma unroll
        for (int y = y0; y < 32; y += 8)
            tile[y][x] = ptr_time[(size_t)(bt * 32 + y) * NN + pt * 32 + x];
        __syncthreads();
        #pragma unroll
        for (int y = y0; y < 32; y += 8)
            g_tP[(size_t)(pt * 32 + y) * BB + bt * 32 + x] = tile[x][y];
    } else if (bid < 3072) {
        // Lt: warp computes 4 rows x 32 cols. 8192 warps total.
        int wg = (bid - 2048) * 8 + (t >> 5);   // 0..8191
        int j = t & 31;
        int r0 = wg * 4;
        const float4* l0 = (const float4*)(lstm + (size_t)r0 * 64);
        float a0 = 0.f, a1 = 0.f, a2 = 0.f, a3 = 0.f;
        #pragma unroll
        for (int k4 = 0; k4 < 16; k4++) {
            float4 v0 = __ldg(l0 + k4);
            float4 v1 = __ldg(l0 + 16 + k4);
            float4 v2 = __ldg(l0 + 32 + k4);
            float4 v3 = __ldg(l0 + 48 + k4);
            float w0 = __ldg(pw + (64 + 4 * k4 + 0) * 32 + j);
            float w1 = __ldg(pw + (64 + 4 * k4 + 1) * 32 + j);
            float w2 = __ldg(pw + (64 + 4 * k4 + 2) * 32 + j);
            float w3 = __ldg(pw + (64 + 4 * k4 + 3) * 32 + j);
            a0 += v0.x * w0 + v0.y * w1 + v0.z * w2 + v0.w * w3;
            a1 += v1.x * w0 + v1.y * w1 + v1.z * w2 + v1.w * w3;
            a2 += v2.x * w0 + v2.y * w1 + v2.z * w2 + v2.w * w3;
            a3 += v3.x * w0 + v3.y * w1 + v3.z * w2 + v3.w * w3;
        }
        g_Lt[(size_t)(r0 + 0) * 32 + j] = a0;
        g_Lt[(size_t)(r0 + 1) * 32 + j] = a1;
        g_Lt[(size_t)(r0 + 2) * 32 + j] = a2;
        g_Lt[(size_t)(r0 + 3) * 32 + j] = a3;
    } else if (bid < 3104) {
        // F: 8192 outputs, 1 per thread
        int gid = (bid - 3072) * 256 + t;
        int b = gid >> 5, j = gid & 31;
        float s = pbias[j];
        #pragma unroll
        for (int k = 0; k < 64; k++)
            s += __ldg(fn + b * 64 + k) * __ldg(pw + k * 32 + j);
        g_F[b * 32 + j] = s;
    } else if (bid < 4704) {
        // combined pair tables: block = (ta, 25-tb chunk). 200 ta x 8 chunks = 1600 blocks.
        __shared__ float Wlsh[1024];
        __shared__ float blsh[32];
        int bid2 = bid - 3104;
        int ta = bid2 >> 3, tb0 = (bid2 & 7) * 25;
        int j = t & 31, tl0 = t >> 5;
        #pragma unroll
        for (int rep = 0; rep < 4; rep++) {
            int idx = t + rep * 256;
            int i = idx >> 5, jj = idx & 31;
            float s = 0.f;
            for (int k = 0; k < 32; k++) s += lw1[i * 32 + k] * lw2[k * 32 + jj];
            Wlsh[idx] = s;
        }
        if (t < 32) {
            float bsum = lb2[t];
            for (int k = 0; k < 32; k++) bsum += lb1[k] * lw2[k * 32 + t];
            blsh[t] = bsum;
        }
        __syncthreads();
        float pa = node_b[j], la = blsh[j];
        #pragma unroll
        for (int e = 0; e < 16; e++) {
            float ev = __ldg(emb + ta * 16 + e);
            pa += ev * node_w[e * 32 + j];
            la += ev * Wlsh[e * 32 + j];
        }
        #pragma unroll
        for (int it = 0; it < 4; it++) {
            int tbl = tl0 + it * 8;
            if (tbl < 25) {
                int tbv = tb0 + tbl;
                float pb = 0.f, lb = 0.f;
                #pragma unroll
                for (int e = 0; e < 16; e++) {
                    float ev = __ldg(emb + tbv * 16 + e);
                    pb += ev * node_w[(16 + e) * 32 + j];
                    lb += ev * Wlsh[(16 + e) * 32 + j];
                }
                size_t o = ((size_t)ta * VOC + tbv) * 32 + j;
                g_PcH[o] = __float2half(pa + pb);
                g_LcH[o] = __float2half(la + lb);
            }
        }
    } else {
        __shared__ int sc[256];
        __shared__ float u[32];
        __shared__ float Wlsh[1024];
        __shared__ float blsh[32];
        for (int i = t; i < NN; i += 256) { g_cnt[i] = 0; g_cur[i] = 0; }
        if (t < 8) g_lvcnt[t] = 0;
        __syncthreads();
        for (int c = t; c < NN; c += 256)
            if (c >= 1) atomicAdd(&g_cnt[parent[c]], 1);
        __syncthreads();
        int base = t * 16;
        int loc[16];
        int run = 0;
        #pragma unroll
        for (int r = 0; r < 16; r++) { loc[r] = run; run += g_cnt[base + r]; }
        sc[t] = run;
        __syncthreads();
        for (int off = 1; off < 256; off <<= 1) {
            int v = (t >= off) ? sc[t - off] : 0;
            __syncthreads();
            sc[t] += v;
            __syncthreads();
        }
        int excl = sc[t] - run;
        #pragma unroll
        for (int r = 0; r < 16; r++) g_off[base + r] = excl + loc[r];
        if (t == 255) g_off[NN] = sc[255];
        __syncthreads();
        for (int c = t; c < NN; c += 256) {
            if (c >= 1) {
                int p = parent[c];
                int pos = atomicAdd(&g_cur[p], 1);
                g_child[g_off[p] + pos] = c;
            }
            int h = height[c];
            if (h < 6) {
                int i = atomicAdd(&g_lvcnt[h], 1);
                g_lvnodes[h * NN + i] = c;
            }
        }
        for (int idx = t; idx < 1024; idx += 256) {
            int i = idx >> 5, j = idx & 31;
            float s = 0.f;
            for (int k = 0; k < 32; k++) s += lw1[i * 32 + k] * lw2[k * 32 + j];
            Wlsh[idx] = s;
        }
        if (t < 32) {
            float bsum = lb2[t];
            for (int k = 0; k < 32; k++) bsum += lb1[k] * lw2[k * 32 + t];
            blsh[t] = bsum;
            float uu = 0.f;
            for (int q = 0; q < 32; q++) uu += fw2[t * 32 + q] * tw[q];
            u[t] = uu;
        }
        __syncthreads();
        if (t < 32) {
            float vv = 0.f;
            for (int k = 0; k < 32; k++) vv += fw1[t * 32 + k] * u[k];
            g_v[t] = vv;
        }
        if (t == 0) {
            float ss = tb[0];
            for (int k = 0; k < 32; k++) ss += fb1[k] * u[k];
            for (int q = 0; q < 32; q++) ss += fb2[q] * tw[q];
            g_s = ss;
        }
        for (int idx = t; idx < VOC * 32; idx += 256) {
            int v = idx >> 5, jj = idx & 31;
            float pa = node_b[jj], pb = 0.f;
            for (int e = 0; e < 16; e++) {
                float ev = emb[v * 16 + e];
                pa += ev * node_w[e * 32 + jj];
                pb += ev * node_w[(16 + e) * 32 + jj];
            }
            g_Pa[idx] = pa;
            g_Pb[idx] = pb;
        }
    }
}

// ============ leaf init: single combined fp16 gather ============
__global__ void __launch_bounds__(256, 4) k_init(const int* __restrict__ kind) {
    int cnt = g_lvcnt[0];
    int b = threadIdx.x;
    for (int ni = blockIdx.x; ni < cnt; ni += gridDim.x) {
        int node = g_lvnodes[ni];
        int kd = kind[node];
        float4 r[8];
        if (kd == 0) {
            int tc = g_tC[node * BB + b];
            unsigned long long o[16];
            gather_one_h(g_LcH, tc, o);
            #pragma unroll
            for (int q = 0; q < 8; q++) {
                float x0, x1, x2, x3;
                unpack2(o[2 * q], x0, x1);
                unpack2(o[2 * q + 1], x2, x3);
                r[q] = make_float4(x0, x1, x2, x3);
            }
        } else {
            int tm = g_tP[node * BB + b];
            const float4* A  = (const float4*)(g_F + b * 32);
            const float4* Bv = (const float4*)(g_Lt + ((size_t)b * TT + tm) * 32);
            #pragma unroll
            for (int q = 0; q < 8; q++) {
                float4 x = A[q], y = Bv[q];
                r[q] = make_float4(x.x + y.x, x.y + y.y, x.z + y.z, x.w + y.w);
            }
        }
        float4* dst = g_h4 + (size_t)node * 2048 + b;
        #pragma unroll
        for (int q = 0; q < 8; q++) dst[q * 256] = r[q];
    }
}

// ============ level: R14 body exactly — syncs retained as scheduling fences ============
__global__ void __launch_bounds__(128, 5) k_level(const float* __restrict__ node_w, int lvl) {
    __shared__ __align__(16) unsigned long long Wsh[512];   // 4KB
    __shared__ float csum[256 * 35];                        // 35.8KB
    int cnt = g_lvcnt[lvl];
    int t = threadIdx.x;
    if ((int)blockIdx.x >= cnt) return;
    ((ulonglong2*)Wsh)[t]       = ((const ulonglong2*)(node_w + 1024))[t];
    ((ulonglong2*)Wsh)[t + 128] = ((const ulonglong2*)(node_w + 1024))[t + 128];
    const int* list = g_lvnodes + lvl * NN;
    for (int ni = blockIdx.x; ni < cnt; ni += gridDim.x) {
        int node = list[ni];
        int c0 = g_off[node], c1 = g_off[node + 1];
        int tc0 = g_tC[node * BB + t];              // hoisted: overlap with child chain
        int tc1 = g_tC[node * BB + t + 128];
        // phase 1: children sums for b=t and b=t+128, staged to smem
        #pragma unroll
        for (int hf = 0; hf < 2; hf++) {
            int b = t + hf * 128;
            float4 a[8];
            #pragma unroll
            for (int q = 0; q < 8; q++) a[q] = make_float4(0.f, 0.f, 0.f, 0.f);
            for (int ci = c0; ci < c1; ci++) {
                int c = g_child[ci];
                const float4* src = g_h4 + (size_t)c * 2048 + b;
                #pragma unroll
                for (int q = 0; q < 8; q++) {
                    float4 v = src[q * 256];
                    a[q].x += v.x; a[q].y += v.y; a[q].z += v.z; a[q].w += v.w;
                }
            }
            const float* af = (const float*)a;
            #pragma unroll
            for (int k = 0; k < 32; k++) csum[b * 35 + k] = af[k];
        }
        __syncthreads();
        // phase 2: single combined gathers + dual matvec
        int b0 = t, b1 = t + 128;
        unsigned long long oA[16], oB[16];
        gather_one_h(g_PcH, tc0, oA);
        gather_one_h(g_PcH, tc1, oB);
        #pragma unroll
        for (int kk = 0; kk < 32; kk++) {
            float s0 = csum[b0 * 35 + kk];
            float s1 = csum[b1 * 35 + kk];
            unsigned long long a0 = pack2(s0, s0);
            unsigned long long a1 = pack2(s1, s1);
            const ulonglong2* wrow = (const ulonglong2*)(Wsh + kk * 16);
            #pragma unroll
            for (int j2 = 0; j2 < 8; j2++) {
                ulonglong2 w = wrow[j2];
                fma2(oA[2 * j2], a0, w.x);
                fma2(oA[2 * j2 + 1], a0, w.y);
                fma2(oB[2 * j2], a1, w.x);
                fma2(oB[2 * j2 + 1], a1, w.y);
            }
        }
        float4* d0 = g_h4 + (size_t)node * 2048 + b0;
        float4* d1 = g_h4 + (size_t)node * 2048 + b1;
        #pragma unroll
        for (int q = 0; q < 8; q++) {
            float l0, h0, l1, h1;
            unpack2(oA[2 * q], l0, h0);
            unpack2(oA[2 * q + 1], l1, h1);
            d0[q * 256] = make_float4(fmaxf(l0, 0.f), fmaxf(h0, 0.f),
                                      fmaxf(l1, 0.f), fmaxf(h1, 0.f));
            unpack2(oB[2 * q], l0, h0);
            unpack2(oB[2 * q + 1], l1, h1);
            d1[q * 256] = make_float4(fmaxf(l0, 0.f), fmaxf(h0, 0.f),
                                      fmaxf(l1, 0.f), fmaxf(h1, 0.f));
        }
        __syncthreads();
    }
}

// ============ root partial sums (128 blocks) ============
__global__ void __launch_bounds__(256) k_f1() {
    int b = threadIdx.x, s = blockIdx.x;
    float4 acc[8];
    #pragma unroll
    for (int q = 0; q < 8; q++) acc[q] = make_float4(0.f, 0.f, 0.f, 0.f);
    int c0 = g_off[0], c1 = g_off[1];
    for (int ci = c0 + s; ci < c1; ci += 128) {
        int c = g_child[ci];
        const float4* src = g_h4 + (size_t)c * 2048 + b;
        #pragma unroll
        for (int q = 0; q < 8; q++) {
            float4 v = src[q * 256];
            acc[q].x += v.x; acc[q].y += v.y; acc[q].z += v.z; acc[q].w += v.w;
        }
    }
    float4* dst = g_p4 + (size_t)s * 2048 + b;
    #pragma unroll
    for (int q = 0; q < 8; q++) dst[q * 256] = acc[q];
}

// ============ root stage 2: 128 -> 16 partials ============
__global__ void __launch_bounds__(256) k_f2() {
    int b = threadIdx.x, s = blockIdx.x;      // s in 0..15
    float4 acc[8];
    #pragma unroll
    for (int q = 0; q < 8; q++) acc[q] = make_float4(0.f, 0.f, 0.f, 0.f);
    #pragma unroll
    for (int i = 0; i < 8; i++) {
        const float4* src = g_p4 + (size_t)(s + 16 * i) * 2048 + b;
        #pragma unroll
        for (int q = 0; q < 8; q++) {
            float4 v = src[q * 256];
            acc[q].x += v.x; acc[q].y += v.y; acc[q].z += v.z; acc[q].w += v.w;
        }
    }
    float4* dst = g_p4 + (size_t)s * 2048 + b;
    #pragma unroll
    for (int q = 0; q < 8; q++) dst[q * 256] = acc[q];
}

// ============ root finish (1 block, 16 partials, fp32 tables) ============
__global__ void __launch_bounds__(256) k_f23(const float* __restrict__ node_w,
                                             float* __restrict__ out) {
    int b = threadIdx.x;
    float4 acc[8];
    #pragma unroll
    for (int q = 0; q < 8; q++) acc[q] = make_float4(0.f, 0.f, 0.f, 0.f);
    #pragma unroll
    for (int s = 0; s < 16; s++) {
        const float4* src = g_p4 + (size_t)s * 2048 + b;
        #pragma unroll
        for (int q = 0; q < 8; q++) {
            float4 v = src[q * 256];
            acc[q].x += v.x; acc[q].y += v.y; acc[q].z += v.z; acc[q].w += v.w;
        }
    }
    int tc = g_tC[b];                       // node 0, batch b
    int ta = tc / VOC, tb = tc - (tc / VOC) * VOC;
    unsigned long long o2[16];
    #pragma unroll
    for (int q = 0; q < 8; q++) {
        ulonglong2 x = ((const ulonglong2*)(g_Pa + ta * 32))[q];
        ulonglong2 y = ((const ulonglong2*)(g_Pb + tb * 32))[q];
        o2[2 * q]     = add2(x.x, y.x);
        o2[2 * q + 1] = add2(x.y, y.y);
    }
    const float* af = (const float*)acc;
    #pragma unroll
    for (int k = 0; k < 32; k++) {
        unsigned long long a2 = pack2(af[k], af[k]);
        const ulonglong2* wrow = (const ulonglong2*)(node_w + 1024 + k * 32);
        #pragma unroll
        for (int j2 = 0; j2 < 8; j2++) {
            ulonglong2 w = wrow[j2];
            fma2(o2[2 * j2], a2, w.x);
            fma2(o2[2 * j2 + 1], a2, w.y);
        }
    }
    float val = 0.f;
    #pragma unroll
    for (int q = 0; q < 8; q++) {
        float l0, h0, l1, h1;
        unpack2(o2[2 * q], l0, h0);
        unpack2(o2[2 * q + 1], l1, h1);
        val += fmaxf(l0, 0.f) * g_v[4 * q]     + fmaxf(h0, 0.f) * g_v[4 * q + 1]
             + fmaxf(l1, 0.f) * g_v[4 * q + 2] + fmaxf(h1, 0.f) * g_v[4 * q + 3];
    }
    out[b] = val + g_s;
}

// ---------------- launch ----------------
extern "C" void kernel_launch(void* const* d_in, const int* in_sizes, int n_in,
                              void* d_out, int out_size) {
    const int*   kind        = (const int*)d_in[0];
    const int*   height      = (const int*)d_in[1];
    const int*   parent      = (const int*)d_in[2];
    const int*   tok_a       = (const int*)d_in[3];
    const int*   tok_b       = (const int*)d_in[4];
    const int*   ptr_time    = (const int*)d_in[5];
    const float* first_notes = (const float*)d_in[6];
    const float* lstm_out    = (const float*)d_in[7];
    const float* embedding   = (const float*)d_in[8];
    const float* leaf_w1     = (const float*)d_in[9];
    const float* leaf_b1     = (const float*)d_in[10];
    const float* leaf_w2     = (const float*)d_in[11];
    const float* leaf_b2     = (const float*)d_in[12];
    const float* node_w      = (const float*)d_in[13];
    const float* node_b      = (const float*)d_in[14];
    const float* ptr_w       = (const float*)d_in[15];
    const float* ptr_b       = (const float*)d_in[16];
    const float* ff_w1       = (const float*)d_in[17];
    const float* ff_b1       = (const float*)d_in[18];
    const float* ff_w2       = (const float*)d_in[19];
    const float* ff_b2       = (const float*)d_in[20];
    const float* tail_w      = (const float*)d_in[21];
    const float* tail_b      = (const float*)d_in[22];
    float* out = (float*)d_out;

    k_prep<<<4705, 256>>>(parent, height, tok_a, tok_b, ptr_time,
                          lstm_out, first_notes, ptr_w, ptr_b,
                          leaf_w1, leaf_b1, leaf_w2, leaf_b2,
                          ff_w1, ff_b1, ff_w2, ff_b2, tail_w, tail_b,
                          embedding, node_w, node_b);
    k_init<<<LVG, 256>>>(kind);
    for (int lvl = 1; lvl <= 5; lvl++)
        k_level<<<LVG, 128>>>(node_w, lvl);
    k_f1<<<128, 256>>>();
    k_f2<<<16, 256>>>();
    k_f23<<<1, 256>>>(node_w, out);
}

// round 17
// speedup vs baseline: 1.4996x; 1.0625x over previous
#include <cuda_runtime.h>
#include <cuda_fp16.h>

#define NN    4096
#define BB    256
#define VOC   200
#define TT    128
#define LVG   740
#define NPAIR (VOC * VOC)

// ---------------- scratch (device globals; no allocation) ----------------
static __device__ uint4 g_hH4[(size_t)NN * 4 * BB];      // fp16 node states [node][q][b], 64MB
static __device__ float4 g_p4[128 * 8 * BB];             // root partials (fp32)
static __device__ float g_Pa[VOC * 32];                  // fp32 (root use)
static __device__ float g_Pb[VOC * 32];
static __device__ __align__(16) __half g_PcH[(size_t)NPAIR * 32];  // combined pair table
static __device__ __align__(16) __half g_LcH[(size_t)NPAIR * 32];  // combined leaf table
static __device__ float g_F[BB * 32];
static __device__ float g_Lt[(size_t)BB * TT * 32];
static __device__ float g_v[32];
static __device__ float g_s;
static __device__ int   g_cnt[NN];
static __device__ int   g_cur[NN];
static __device__ int   g_off[NN + 1];
static __device__ int   g_child[NN];
static __device__ int   g_lvcnt[8];
static __device__ int   g_lvnodes[6 * NN];
static __device__ int   g_tC[NN * BB];                   // fused ta*200+tb, [p][b]
static __device__ int   g_tP[NN * BB];

// ---------------- f32x2 helpers ----------------
__device__ __forceinline__ unsigned long long pack2(float lo, float hi) {
    unsigned long long r;
    asm("mov.b64 %0, {%1, %2};" : "=l"(r) : "r"(__float_as_uint(lo)), "r"(__float_as_uint(hi)));
    return r;
}
__device__ __forceinline__ void unpack2(unsigned long long v, float& lo, float& hi) {
    unsigned int a, b;
    asm("mov.b64 {%0, %1}, %2;" : "=r"(a), "=r"(b) : "l"(v));
    lo = __uint_as_float(a);
    hi = __uint_as_float(b);
}
__device__ __forceinline__ void fma2(unsigned long long& d, unsigned long long a, unsigned long long b) {
    asm("fma.rn.f32x2 %0, %1, %2, %0;" : "+l"(d) : "l"(a), "l"(b));
}
__device__ __forceinline__ unsigned long long add2(unsigned long long a, unsigned long long b) {
    unsigned long long r;
    asm("add.rn.f32x2 %0, %1, %2;" : "=l"(r) : "l"(a), "l"(b));
    return r;
}
__device__ __forceinline__ unsigned pack_h2(float a, float b) {
    __half2 h = __floats2half2_rn(a, b);
    return *reinterpret_cast<unsigned*>(&h);
}

// gather ONE fp16 combined row -> 16 packed f32x2
__device__ __forceinline__ void gather_one_h(const __half* Pc, int tc, unsigned long long* o) {
    const uint4* A = (const uint4*)(Pc + (size_t)tc * 32);
    #pragma unroll
    for (int q = 0; q < 4; q++) {
        uint4 x = A[q];
        unsigned xs[4] = {x.x, x.y, x.z, x.w};
        #pragma unroll
        for (int r = 0; r < 4; r++) {
            float2 f = __half22float2(*(const __half2*)&xs[r]);
            o[q * 4 + r] = pack2(f.x, f.y);
        }
    }
}

// accumulate one fp16 h row (child c, batch b) into feature-indexed acc[32]
__device__ __forceinline__ void accum_h16(float* acc, int c, int b) {
    const uint4* src = g_hH4 + (size_t)c * 1024 + b;
    #pragma unroll
    for (int q = 0; q < 4; q++) {
        uint4 v = src[q * 256];
        unsigned ws[4] = {v.x, v.y, v.z, v.w};
        #pragma unroll
        for (int r = 0; r < 4; r++) {
            float2 f = __half22float2(*(const __half2*)&ws[r]);
            acc[q * 8 + r * 2]     += f.x;
            acc[q * 8 + r * 2 + 1] += f.y;
        }
    }
}

// ============ prep roles:
//   [0,1024)    fused token transpose -> g_tC
//   [1024,2048) ptr_time transpose   -> g_tP
//   [2048,3072) Lt
//   [3072,3104) F
//   [3104,4704) combined pair tables (PcH/LcH)
//   4704        serial: CSR/scan/fuse/root-tables
__global__ void __launch_bounds__(256) k_prep(
    const int* __restrict__ parent, const int* __restrict__ height,
    const int* __restrict__ tok_a, const int* __restrict__ tok_b,
    const int* __restrict__ ptr_time,
    const float* __restrict__ lstm, const float* __restrict__ fn,
    const float* __restrict__ pw, const float* __restrict__ pbias,
    const float* __restrict__ lw1, const float* __restrict__ lb1,
    const float* __restrict__ lw2, const float* __restrict__ lb2,
    const float* __restrict__ fw1, const float* __restrict__ fb1,
    const float* __restrict__ fw2, const float* __restrict__ fb2,
    const float* __restrict__ tw, const float* __restrict__ tb,
    const float* __restrict__ emb, const float* __restrict__ node_w,
    const float* __restrict__ node_b)
{
    int bid = blockIdx.x, t = threadIdx.x;
    if (bid < 1024) {
        __shared__ int tile[32][33];
        int pt = bid >> 3, bt = bid & 7;
        int x = t & 31, y0 = t >> 5;
        #pragma unroll
        for (int y = y0; y < 32; y += 8) {
            size_t idx = (size_t)(bt * 32 + y) * NN + pt * 32 + x;
            tile[y][x] = tok_a[idx] * VOC + tok_b[idx];
        }
        __syncthreads();
        #pragma unroll
        for (int y = y0; y < 32; y += 8)
            g_tC[(size_t)(pt * 32 + y) * BB + bt * 32 + x] = tile[x][y];
    } else if (bid < 2048) {
        __shared__ int tile[32][33];
        int tl = bid - 1024;
        int pt = tl >> 3, bt = tl & 7;
        int x = t & 31, y0 = t >> 5;
        #pragma unroll
        for (int y = y0; y < 32; y += 8)
            tile[y][x] = ptr_time[(size_t)(bt * 32 + y) * NN + pt * 32 + x];
        __syncthreads();
        #pragma unroll
        for (int y = y0; y < 32; y += 8)
            g_tP[(size_t)(pt * 32 + y) * BB + bt * 32 + x] = tile[x][y];
    } else if (bid < 3072) {
        int wg = (bid - 2048) * 8 + (t >> 5);   // 0..8191
        int j = t & 31;
        int r0 = wg * 4;
        const float4* l0 = (const float4*)(lstm + (size_t)r0 * 64);
        float a0 = 0.f, a1 = 0.f, a2 = 0.f, a3 = 0.f;
        #pragma unroll
        for (int k4 = 0; k4 < 16; k4++) {
            float4 v0 = __ldg(l0 + k4);
            float4 v1 = __ldg(l0 + 16 + k4);
            float4 v2 = __ldg(l0 + 32 + k4);
            float4 v3 = __ldg(l0 + 48 + k4);
            float w0 = __ldg(pw + (64 + 4 * k4 + 0) * 32 + j);
            float w1 = __ldg(pw + (64 + 4 * k4 + 1) * 32 + j);
            float w2 = __ldg(pw + (64 + 4 * k4 + 2) * 32 + j);
            float w3 = __ldg(pw + (64 + 4 * k4 + 3) * 32 + j);
            a0 += v0.x * w0 + v0.y * w1 + v0.z * w2 + v0.w * w3;
            a1 += v1.x * w0 + v1.y * w1 + v1.z * w2 + v1.w * w3;
            a2 += v2.x * w0 + v2.y * w1 + v2.z * w2 + v2.w * w3;
            a3 += v3.x * w0 + v3.y * w1 + v3.z * w2 + v3.w * w3;
        }
        g_Lt[(size_t)(r0 + 0) * 32 + j] = a0;
        g_Lt[(size_t)(r0 + 1) * 32 + j] = a1;
        g_Lt[(size_t)(r0 + 2) * 32 + j] = a2;
        g_Lt[(size_t)(r0 + 3) * 32 + j] = a3;
    } else if (bid < 3104) {
        int gid = (bid - 3072) * 256 + t;
        int b = gid >> 5, j = gid & 31;
        float s = pbias[j];
        #pragma unroll
        for (int k = 0; k < 64; k++)
            s += __ldg(fn + b * 64 + k) * __ldg(pw + k * 32 + j);
        g_F[b * 32 + j] = s;
    } else if (bid < 4704) {
        __shared__ float Wlsh[1024];
        __shared__ float blsh[32];
        int bid2 = bid - 3104;
        int ta = bid2 >> 3, tb0 = (bid2 & 7) * 25;
        int j = t & 31, tl0 = t >> 5;
        #pragma unroll
        for (int rep = 0; rep < 4; rep++) {
            int idx = t + rep * 256;
            int i = idx >> 5, jj = idx & 31;
            float s = 0.f;
            for (int k = 0; k < 32; k++) s += lw1[i * 32 + k] * lw2[k * 32 + jj];
            Wlsh[idx] = s;
        }
        if (t < 32) {
            float bsum = lb2[t];
            for (int k = 0; k < 32; k++) bsum += lb1[k] * lw2[k * 32 + t];
            blsh[t] = bsum;
        }
        __syncthreads();
        float pa = node_b[j], la = blsh[j];
        #pragma unroll
        for (int e = 0; e < 16; e++) {
            float ev = __ldg(emb + ta * 16 + e);
            pa += ev * node_w[e * 32 + j];
            la += ev * Wlsh[e * 32 + j];
        }
        #pragma unroll
        for (int it = 0; it < 4; it++) {
            int tbl = tl0 + it * 8;
            if (tbl < 25) {
                int tbv = tb0 + tbl;
                float pb = 0.f, lb = 0.f;
                #pragma unroll
                for (int e = 0; e < 16; e++) {
                    float ev = __ldg(emb + tbv * 16 + e);
                    pb += ev * node_w[(16 + e) * 32 + j];
                    lb += ev * Wlsh[(16 + e) * 32 + j];
                }
                size_t o = ((size_t)ta * VOC + tbv) * 32 + j;
                g_PcH[o] = __float2half(pa + pb);
                g_LcH[o] = __float2half(la + lb);
            }
        }
    } else {
        __shared__ int sc[256];
        __shared__ float u[32];
        __shared__ float Wlsh[1024];
        __shared__ float blsh[32];
        for (int i = t; i < NN; i += 256) { g_cnt[i] = 0; g_cur[i] = 0; }
        if (t < 8) g_lvcnt[t] = 0;
        __syncthreads();
        for (int c = t; c < NN; c += 256)
            if (c >= 1) atomicAdd(&g_cnt[parent[c]], 1);
        __syncthreads();
        int base = t * 16;
        int loc[16];
        int run = 0;
        #pragma unroll
        for (int r = 0; r < 16; r++) { loc[r] = run; run += g_cnt[base + r]; }
        sc[t] = run;
        __syncthreads();
        for (int off = 1; off < 256; off <<= 1) {
            int v = (t >= off) ? sc[t - off] : 0;
            __syncthreads();
            sc[t] += v;
            __syncthreads();
        }
        int excl = sc[t] - run;
        #pragma unroll
        for (int r = 0; r < 16; r++) g_off[base + r] = excl + loc[r];
        if (t == 255) g_off[NN] = sc[255];
        __syncthreads();
        for (int c = t; c < NN; c += 256) {
            if (c >= 1) {
                int p = parent[c];
                int pos = atomicAdd(&g_cur[p], 1);
                g_child[g_off[p] + pos] = c;
            }
            int h = height[c];
            if (h < 6) {
                int i = atomicAdd(&g_lvcnt[h], 1);
                g_lvnodes[h * NN + i] = c;
            }
        }
        for (int idx = t; idx < 1024; idx += 256) {
            int i = idx >> 5, j = idx & 31;
            float s = 0.f;
            for (int k = 0; k < 32; k++) s += lw1[i * 32 + k] * lw2[k * 32 + j];
            Wlsh[idx] = s;
        }
        if (t < 32) {
            float bsum = lb2[t];
            for (int k = 0; k < 32; k++) bsum += lb1[k] * lw2[k * 32 + t];
            blsh[t] = bsum;
            float uu = 0.f;
            for (int q = 0; q < 32; q++) uu += fw2[t * 32 + q] * tw[q];
            u[t] = uu;
        }
        __syncthreads();
        if (t < 32) {
            float vv = 0.f;
            for (int k = 0; k < 32; k++) vv += fw1[t * 32 + k] * u[k];
            g_v[t] = vv;
        }
        if (t == 0) {
            float ss = tb[0];
            for (int k = 0; k < 32; k++) ss += fb1[k] * u[k];
            for (int q = 0; q < 32; q++) ss += fb2[q] * tw[q];
            g_s = ss;
        }
        for (int idx = t; idx < VOC * 32; idx += 256) {
            int v = idx >> 5, jj = idx & 31;
            float pa = node_b[jj], pb = 0.f;
            for (int e = 0; e < 16; e++) {
                float ev = emb[v * 16 + e];
                pa += ev * node_w[e * 32 + jj];
                pb += ev * node_w[(16 + e) * 32 + jj];
            }
            g_Pa[idx] = pa;
            g_Pb[idx] = pb;
        }
    }
}

// ============ leaf init: kind-0 = raw fp16 row copy; kind-1 = fp32 sum -> fp16 ============
__global__ void __launch_bounds__(256, 4) k_init(const int* __restrict__ kind) {
    int cnt = g_lvcnt[0];
    int b = threadIdx.x;
    for (int ni = blockIdx.x; ni < cnt; ni += gridDim.x) {
        int node = g_lvnodes[ni];
        int kd = kind[node];
        uint4* dst = g_hH4 + (size_t)node * 1024 + b;
        if (kd == 0) {
            int tc = g_tC[node * BB + b];
            const uint4* A = (const uint4*)(g_LcH + (size_t)tc * 32);
            #pragma unroll
            for (int q = 0; q < 4; q++) dst[q * 256] = A[q];
        } else {
            int tm = g_tP[node * BB + b];
            const float4* A  = (const float4*)(g_F + b * 32);
            const float4* Bv = (const float4*)(g_Lt + ((size_t)b * TT + tm) * 32);
            #pragma unroll
            for (int q = 0; q < 4; q++) {
                float4 x0 = A[2 * q],     y0 = Bv[2 * q];
                float4 x1 = A[2 * q + 1], y1 = Bv[2 * q + 1];
                uint4 s;
                s.x = pack_h2(x0.x + y0.x, x0.y + y0.y);
                s.y = pack_h2(x0.z + y0.z, x0.w + y0.w);
                s.z = pack_h2(x1.x + y1.x, x1.y + y1.y);
                s.w = pack_h2(x1.z + y1.z, x1.w + y1.w);
                dst[q * 256] = s;
            }
        }
    }
}

// ============ level: fp16 h, 128 thr/node, (128,5), stride-35 csum, syncs retained ============
__global__ void __launch_bounds__(128, 5) k_level(const float* __restrict__ node_w, int lvl) {
    __shared__ __align__(16) unsigned long long Wsh[512];   // 4KB
    __shared__ float csum[256 * 35];                        // 35.8KB
    int cnt = g_lvcnt[lvl];
    int t = threadIdx.x;
    if ((int)blockIdx.x >= cnt) return;
    ((ulonglong2*)Wsh)[t]       = ((const ulonglong2*)(node_w + 1024))[t];
    ((ulonglong2*)Wsh)[t + 128] = ((const ulonglong2*)(node_w + 1024))[t + 128];
    const int* list = g_lvnodes + lvl * NN;
    for (int ni = blockIdx.x; ni < cnt; ni += gridDim.x) {
        int node = list[ni];
        int c0 = g_off[node], c1 = g_off[node + 1];
        int tc0 = g_tC[node * BB + t];
        int tc1 = g_tC[node * BB + t + 128];
        // phase 1: children sums (fp16 loads, fp32 accumulate), staged to smem
        #pragma unroll
        for (int hf = 0; hf < 2; hf++) {
            int b = t + hf * 128;
            float acc[32];
            #pragma unroll
            for (int i = 0; i < 32; i++) acc[i] = 0.f;
            for (int ci = c0; ci < c1; ci++)
                accum_h16(acc, g_child[ci], b);
            #pragma unroll
            for (int k = 0; k < 32; k++) csum[b * 35 + k] = acc[k];
        }
        __syncthreads();
        // phase 2: single combined gathers + dual matvec
        int b0 = t, b1 = t + 128;
        unsigned long long oA[16], oB[16];
        gather_one_h(g_PcH, tc0, oA);
        gather_one_h(g_PcH, tc1, oB);
        #pragma unroll
        for (int kk = 0; kk < 32; kk++) {
            float s0 = csum[b0 * 35 + kk];
            float s1 = csum[b1 * 35 + kk];
            unsigned long long a0 = pack2(s0, s0);
            unsigned long long a1 = pack2(s1, s1);
            const ulonglong2* wrow = (const ulonglong2*)(Wsh + kk * 16);
            #pragma unroll
            for (int j2 = 0; j2 < 8; j2++) {
                ulonglong2 w = wrow[j2];
                fma2(oA[2 * j2], a0, w.x);
                fma2(oA[2 * j2 + 1], a0, w.y);
                fma2(oB[2 * j2], a1, w.x);
                fma2(oB[2 * j2 + 1], a1, w.y);
            }
        }
        // relu + fp16 pack + store
        uint4* d0 = g_hH4 + (size_t)node * 1024 + b0;
        uint4* d1 = g_hH4 + (size_t)node * 1024 + b1;
        #pragma unroll
        for (int q = 0; q < 4; q++) {
            float l0, h0, l1, h1, l2, h2, l3, h3;
            unpack2(oA[4 * q],     l0, h0);
            unpack2(oA[4 * q + 1], l1, h1);
            unpack2(oA[4 * q + 2], l2, h2);
            unpack2(oA[4 * q + 3], l3, h3);
            uint4 s;
            s.x = pack_h2(fmaxf(l0, 0.f), fmaxf(h0, 0.f));
            s.y = pack_h2(fmaxf(l1, 0.f), fmaxf(h1, 0.f));
            s.z = pack_h2(fmaxf(l2, 0.f), fmaxf(h2, 0.f));
            s.w = pack_h2(fmaxf(l3, 0.f), fmaxf(h3, 0.f));
            d0[q * 256] = s;
            unpack2(oB[4 * q],     l0, h0);
            unpack2(oB[4 * q + 1], l1, h1);
            unpack2(oB[4 * q + 2], l2, h2);
            unpack2(oB[4 * q + 3], l3, h3);
            s.x = pack_h2(fmaxf(l0, 0.f), fmaxf(h0, 0.f));
            s.y = pack_h2(fmaxf(l1, 0.f), fmaxf(h1, 0.f));
            s.z = pack_h2(fmaxf(l2, 0.f), fmaxf(h2, 0.f));
            s.w = pack_h2(fmaxf(l3, 0.f), fmaxf(h3, 0.f));
            d1[q * 256] = s;
        }
        __syncthreads();
    }
}

// ============ root partial sums (128 blocks), fp16 child reads ============
__global__ void __launch_bounds__(256) k_f1() {
    int b = threadIdx.x, s = blockIdx.x;
    float acc[32];
    #pragma unroll
    for (int i = 0; i < 32; i++) acc[i] = 0.f;
    int c0 = g_off[0], c1 = g_off[1];
    for (int ci = c0 + s; ci < c1; ci += 128)
        accum_h16(acc, g_child[ci], b);
    float4* dst = g_p4 + (size_t)s * 2048 + b;
    #pragma unroll
    for (int q = 0; q < 8; q++)
        dst[q * 256] = make_float4(acc[4 * q], acc[4 * q + 1], acc[4 * q + 2], acc[4 * q + 3]);
}

// ============ root stage 2: 128 -> 16 partials ============
__global__ void __launch_bounds__(256) k_f2() {
    int b = threadIdx.x, s = blockIdx.x;      // s in 0..15
    float4 acc[8];
    #pragma unroll
    for (int q = 0; q < 8; q++) acc[q] = make_float4(0.f, 0.f, 0.f, 0.f);
    #pragma unroll
    for (int i = 0; i < 8; i++) {
        const float4* src = g_p4 + (size_t)(s + 16 * i) * 2048 + b;
        #pragma unroll
        for (int q = 0; q < 8; q++) {
            float4 v = src[q * 256];
            acc[q].x += v.x; acc[q].y += v.y; acc[q].z += v.z; acc[q].w += v.w;
        }
    }
    float4* dst = g_p4 + (size_t)s * 2048 + b;
    #pragma unroll
    for (int q = 0; q < 8; q++) dst[q * 256] = acc[q];
}

// ============ root finish (1 block, 16 partials, fp32 tables) ============
__global__ void __launch_bounds__(256) k_f23(const float* __restrict__ node_w,
                                             float* __restrict__ out) {
    int b = threadIdx.x;
    float4 acc[8];
    #pragma unroll
    for (int q = 0; q < 8; q++) acc[q] = make_float4(0.f, 0.f, 0.f, 0.f);
    #pragma unroll
    for (int s = 0; s < 16; s++) {
        const float4* src = g_p4 + (size_t)s * 2048 + b;
        #pragma unroll
        for (int q = 0; q < 8; q++) {
            float4 v = src[q * 256];
            acc[q].x += v.x; acc[q].y += v.y; acc[q].z += v.z; acc[q].w += v.w;
        }
    }
    int tc = g_tC[b];                       // node 0, batch b
    int ta = tc / VOC, tb = tc - (tc / VOC) * VOC;
    unsigned long long o2[16];
    #pragma unroll
    for (int q = 0; q < 8; q++) {
        ulonglong2 x = ((const ulonglong2*)(g_Pa + ta * 32))[q];
        ulonglong2 y = ((const ulonglong2*)(g_Pb + tb * 32))[q];
        o2[2 * q]     = add2(x.x, y.x);
        o2[2 * q + 1] = add2(x.y, y.y);
    }
    const float* af = (const float*)acc;
    #pragma unroll
    for (int k = 0; k < 32; k++) {
        unsigned long long a2 = pack2(af[k], af[k]);
        const ulonglong2* wrow = (const ulonglong2*)(node_w + 1024 + k * 32);
        #pragma unroll
        for (int j2 = 0; j2 < 8; j2++) {
            ulonglong2 w = wrow[j2];
            fma2(o2[2 * j2], a2, w.x);
            fma2(o2[2 * j2 + 1], a2, w.y);
        }
    }
    float val = 0.f;
    #pragma unroll
    for (int q = 0; q < 8; q++) {
        float l0, h0, l1, h1;
        unpack2(o2[2 * q], l0, h0);
        unpack2(o2[2 * q + 1], l1, h1);
        val += fmaxf(l0, 0.f) * g_v[4 * q]     + fmaxf(h0, 0.f) * g_v[4 * q + 1]
             + fmaxf(l1, 0.f) * g_v[4 * q + 2] + fmaxf(h1, 0.f) * g_v[4 * q + 3];
    }
    out[b] = val + g_s;
}

// ---------------- launch ----------------
extern "C" void kernel_launch(void* const* d_in, const int* in_sizes, int n_in,
                              void* d_out, int out_size) {
    const int*   kind        = (const int*)d_in[0];
    const int*   height      = (const int*)d_in[1];
    const int*   parent      = (const int*)d_in[2];
    const int*   tok_a       = (const int*)d_in[3];
    const int*   tok_b       = (const int*)d_in[4];
    const int*   ptr_time    = (const int*)d_in[5];
    const float* first_notes = (const float*)d_in[6];
    const float* lstm_out    = (const float*)d_in[7];
    const float* embedding   = (const float*)d_in[8];
    const float* leaf_w1     = (const float*)d_in[9];
    const float* leaf_b1     = (const float*)d_in[10];
    const float* leaf_w2     = (const float*)d_in[11];
    const float* leaf_b2     = (const float*)d_in[12];
    const float* node_w      = (const float*)d_in[13];
    const float* node_b      = (const float*)d_in[14];
    const float* ptr_w       = (const float*)d_in[15];
    const float* ptr_b       = (const float*)d_in[16];
    const float* ff_w1       = (const float*)d_in[17];
    const float* ff_b1       = (const float*)d_in[18];
    const float* ff_w2       = (const float*)d_in[19];
    const float* ff_b2       = (const float*)d_in[20];
    const float* tail_w      = (const float*)d_in[21];
    const float* tail_b      = (const float*)d_in[22];
    float* out = (float*)d_out;

    k_prep<<<4705, 256>>>(parent, height, tok_a, tok_b, ptr_time,
                          lstm_out, first_notes, ptr_w, ptr_b,
                          leaf_w1, leaf_b1, leaf_w2, leaf_b2,
                          ff_w1, ff_b1, ff_w2, ff_b2, tail_w, tail_b,
                          embedding, node_w, node_b);
    k_init<<<LVG, 256>>>(kind);
    for (int lvl = 1; lvl <= 5; lvl++)
        k_level<<<LVG, 128>>>(node_w, lvl);
    k_f1<<<128, 256>>>();
    k_f2<<<16, 256>>>();
    k_f23<<<1, 256>>>(node_w, out);
}